// round 7
// baseline (speedup 1.0000x reference)
#include <cuda_runtime.h>
#include <cstdint>

// Fixed problem geometry: H=W=2048, step=2 -> nu=nv=1024, N=2^20 nodes.
constexpr int NU = 1024;
constexpr int NV = 1024;
constexpr int N  = NU * NV;
constexpr int W  = 2048;

// Output layout (floats): pts[3N] nrm[3N] radii[N] lens[4N] areas[2N]
constexpr int OFF_PTS  = 0;
constexpr int OFF_NRM  = 3 * N;
constexpr int OFF_RAD  = 6 * N;
constexpr int OFF_LEN  = 7 * N;
constexpr int OFF_AREA = 11 * N;

constexpr int TX = 16;   // threads in x; each thread owns 2 adjacent columns
constexpr int TY = 16;   // threads in y
// tile = 32 cols x 16 rows of nodes per 256-thread block

// Fast sqrt: MUFU.RSQ + FMUL; x==0 -> 0 (guard avoids NaN).
__device__ __forceinline__ float fast_sqrt(float x) {
    return x * rsqrtf(fmaxf(x, 1e-30f));
}

struct F3 { float x, y, z; };

__device__ __forceinline__ F3 loadA(const float* __restrict__ p, int jv, int iu) {
    // anchor (iu, jv): float offset = (2jv*W + 2iu)*3 (int32-safe, 8B aligned)
    int off = jv * (6 * W) + iu * 6;
    float2 ab = *reinterpret_cast<const float2*>(p + off);
    F3 r; r.x = ab.x; r.y = ab.y; r.z = p[off + 2];
    return r;
}

__device__ __forceinline__ float dist3(const F3& a, const F3& b) {
    float dx = a.x - b.x, dy = a.y - b.y, dz = a.z - b.z;
    return fast_sqrt(dx * dx + dy * dy + dz * dz);
}

__device__ __forceinline__ void st2(float* __restrict__ p, int off, float a, float b) {
    *reinterpret_cast<float2*>(p + off) = make_float2(a, b);
}

// ---------------------------------------------------------------------------
// Node-pair kernel: thread handles nodes k (iu even) and k+1. Own distances
// computed once, shared via smem with halo row/col for cross-thread radii.
// ---------------------------------------------------------------------------
__global__ __launch_bounds__(TX * TY)
void k_pair(const float* __restrict__ cand,
            const float* __restrict__ cnrm,
            float* __restrict__ out) {
    __shared__ float sRb[TY + 1][TX + 1];  // dR of node b
    __shared__ float sAb[TY + 1][TX + 1];  // dAo of node b
    __shared__ float sAa[TY + 1][TX + 1];  // dAo of node a
    __shared__ float sDa[TY + 1][TX + 1];  // dD of node a
    __shared__ float sDb[TY + 1][TX + 1];  // dD of node b
    __shared__ float sGa[TY + 1][TX + 1];  // dG of node a
    __shared__ float sGb[TY + 1][TX + 1];  // dG of node b

    const int tid = threadIdx.x;
    const int x = tid & (TX - 1);
    const int y = tid >> 4;
    const int iu0 = blockIdx.x * (2 * TX);
    const int jv0 = blockIdx.y * TY;
    const int iu = iu0 + 2 * x;          // node a column (even)
    const int jv = jv0 + y;
    const int k  = jv * NU + iu;         // even

    const bool de   = jv < NV - 1;
    const bool ue   = jv > 0;
    const bool le_a = iu > 0;
    const bool re_b = iu < NU - 2;       // node b has right neighbor
    const int jvD = de ? jv + 1 : jv;
    const int iu2 = re_b ? iu + 2 : iu + 1;   // clamp (flag-guarded)

    // point window: row jv and row jv+1, columns iu, iu+1, iu+2
    F3 P0 = loadA(cand, jv,  iu);
    F3 P1 = loadA(cand, jv,  iu + 1);
    F3 P2 = loadA(cand, jv,  iu2);
    F3 D0 = loadA(cand, jvD, iu);
    F3 D1 = loadA(cand, jvD, iu + 1);
    F3 D2 = loadA(cand, jvD, iu2);
    F3 Na = loadA(cnrm, jv,  iu);
    F3 Nb = loadA(cnrm, jv,  iu + 1);

    // owned distances (4 per node)
    float dRa = dist3(P0, P1), dGa = dist3(P0, D1), dDa = dist3(P0, D0), dAa = dist3(P1, D0);
    float dRb = dist3(P1, P2), dGb = dist3(P1, D2), dDb = dist3(P1, D1), dAb = dist3(P2, D1);

    sRb[y + 1][x + 1] = dRb;  sAb[y + 1][x + 1] = dAb;  sAa[y + 1][x + 1] = dAa;
    sDa[y + 1][x + 1] = dDa;  sDb[y + 1][x + 1] = dDb;
    sGa[y + 1][x + 1] = dGa;  sGb[y + 1][x + 1] = dGb;

    // top halo: distances of row jv0-1 nodes (down-row = our P row)
    if (y == 0) {
        int jvU = ue ? jv0 - 1 : 0;      // clamp (flag-guarded)
        F3 U0 = loadA(cand, jvU, iu);
        F3 U1 = loadA(cand, jvU, iu + 1);
        F3 U2 = loadA(cand, jvU, iu2);
        sDa[0][x + 1] = dist3(U0, P0);   // dD(iu,   jvU)
        sDb[0][x + 1] = dist3(U1, P1);   // dD(iu+1, jvU)
        sAa[0][x + 1] = dist3(U1, P0);   // dAo(iu,  jvU)
        sAb[0][x + 1] = dist3(U2, P1);   // dAo(iu+1,jvU)
        sGa[0][x + 1] = dist3(U0, P1);   // dG(iu,   jvU)
        sGb[0][x + 1] = dist3(U1, P2);   // dG(iu+1, jvU)
    }
    // left halo: node (iu0-1, jv) distances needed by node a at x==0
    if (x == 0) {
        int iuL = (iu0 > 0) ? iu0 - 1 : 0;   // clamp (flag-guarded)
        F3 L  = loadA(cand, jv,  iuL);
        F3 DL = loadA(cand, jvD, iuL);
        sRb[y + 1][0] = dist3(L, P0);    // dR (iu0-1, jv)
        sAb[y + 1][0] = dist3(P0, DL);   // dAo(iu0-1, jv)
        sGb[y + 1][0] = dist3(L, D0);    // dG (iu0-1, jv)
    }
    // corner: dG(iu0-1, jv0-1)
    if (tid == 0) {
        int iuL = (iu0 > 0) ? iu0 - 1 : 0;
        int jvU = ue ? jv0 - 1 : 0;
        F3 UL = loadA(cand, jvU, iuL);
        sGb[0][0] = dist3(UL, P0);
    }

    // areas (register-only)
    float e1x = P1.x - P0.x, e1y = P1.y - P0.y, e1z = P1.z - P0.z;
    float e2x = D1.x - P0.x, e2y = D1.y - P0.y, e2z = D1.z - P0.z;
    float f2x = D0.x - P0.x, f2y = D0.y - P0.y, f2z = D0.z - P0.z;
    float a0a = 0.5f * fast_sqrt(
        (e1y*e2z - e1z*e2y)*(e1y*e2z - e1z*e2y) +
        (e1z*e2x - e1x*e2z)*(e1z*e2x - e1x*e2z) +
        (e1x*e2y - e1y*e2x)*(e1x*e2y - e1y*e2x) + 1e-13f);
    float a1a = 0.5f * fast_sqrt(
        (e2y*f2z - e2z*f2y)*(e2y*f2z - e2z*f2y) +
        (e2z*f2x - e2x*f2z)*(e2z*f2x - e2x*f2z) +
        (e2x*f2y - e2y*f2x)*(e2x*f2y - e2y*f2x) + 1e-13f);

    float g1x = P2.x - P1.x, g1y = P2.y - P1.y, g1z = P2.z - P1.z;
    float g2x = D2.x - P1.x, g2y = D2.y - P1.y, g2z = D2.z - P1.z;
    float h2x = D1.x - P1.x, h2y = D1.y - P1.y, h2z = D1.z - P1.z;
    float a0b = 0.5f * fast_sqrt(
        (g1y*g2z - g1z*g2y)*(g1y*g2z - g1z*g2y) +
        (g1z*g2x - g1x*g2z)*(g1z*g2x - g1x*g2z) +
        (g1x*g2y - g1y*g2x)*(g1x*g2y - g1y*g2x) + 1e-13f);
    float a1b = 0.5f * fast_sqrt(
        (g2y*h2z - g2z*h2y)*(g2y*h2z - g2z*h2y) +
        (g2z*h2x - g2x*h2z)*(g2z*h2x - g2x*h2z) +
        (g2x*h2y - g2y*h2x)*(g2x*h2y - g2y*h2x) + 1e-13f);

    __syncthreads();

    // --- node a radii (re always true for even iu <= 1022) ---
    float suma = dRa; float cnta = 1.0f;
    if (de)         { suma += dGa + dDa;            cnta += 2.0f; }
    if (le_a && de) { suma += sAb[y + 1][x];        cnta += 1.0f; }  // anti(k-1)
    if (le_a)       { suma += sRb[y + 1][x];        cnta += 1.0f; }  // right(k-1)
    if (le_a && ue) { suma += sGb[y][x];            cnta += 1.0f; }  // diag(k-NU-1)
    if (ue)         { suma += sDa[y][x + 1] + sAa[y][x + 1]; cnta += 2.0f; } // down/anti(k-NU)

    // --- node b radii (le always true) ---
    float sumb = dRa;  float cntb = 1.0f;                            // right(k) from register
    if (de)         { sumb += dDb + dAa;            cntb += 2.0f; }  // down(k+1), anti(k)
    if (re_b)       { sumb += dRb;                  cntb += 1.0f; }
    if (re_b && de) { sumb += dGb;                  cntb += 1.0f; }
    if (ue)         { sumb += sGa[y][x + 1] + sDb[y][x + 1]; cntb += 2.0f; } // diag(k-NU), down(k+1-NU)
    if (re_b && ue) { sumb += sAb[y][x + 1];        cntb += 1.0f; }  // anti(k+1-NU)

    // ---- vectorized outputs (all float2, 8B-aligned: k even) ----
    int p3 = OFF_PTS + 3 * k;
    st2(out, p3 + 0, P0.x, P0.y);
    st2(out, p3 + 2, P0.z, P1.x);
    st2(out, p3 + 4, P1.y, P1.z);
    int n3 = OFF_NRM + 3 * k;
    st2(out, n3 + 0, Na.x, Na.y);
    st2(out, n3 + 2, Na.z, Nb.x);
    st2(out, n3 + 4, Nb.y, Nb.z);
    st2(out, OFF_RAD + k, suma / cnta, sumb / cntb);

    bool rdb = re_b && de;
    st2(out, OFF_LEN + 0 * N + k, dRa,               re_b ? dRb : 0.0f);
    st2(out, OFF_LEN + 1 * N + k, de ? dGa : 0.0f,   rdb ? dGb : 0.0f);
    st2(out, OFF_LEN + 2 * N + k, de ? dDa : 0.0f,   de  ? dDb : 0.0f);
    st2(out, OFF_LEN + 3 * N + k, de ? dAa : 0.0f,   rdb ? dAb : 0.0f);
    st2(out, OFF_AREA + 0 * N + k, de ? a0a : 0.0f,  rdb ? a0b : 0.0f);
    st2(out, OFF_AREA + 1 * N + k, de ? a1a : 0.0f,  rdb ? a1b : 0.0f);
}

// ---------------------------------------------------------------------------
// Launch
// ---------------------------------------------------------------------------
extern "C" void kernel_launch(void* const* d_in, const int* in_sizes, int n_in,
                              void* d_out, int out_size) {
    (void)in_sizes; (void)n_in; (void)out_size;
    const float* cand = (const float*)d_in[1];
    const float* cnrm = (const float*)d_in[2];
    float* out = (float*)d_out;

    dim3 grid(NU / (2 * TX), NV / TY);
    k_pair<<<grid, TX * TY>>>(cand, cnrm, out);
}